// round 2
// baseline (speedup 1.0000x reference)
#include <cuda_runtime.h>
#include <math.h>

#define BATCH  8192
#define NNZ    32
#define FT_OUT 512
#define NTHREADS 128   // each thread owns FT_OUT/NTHREADS = 4 floats (one float4)

__global__ __launch_bounds__(NTHREADS)
void nnue_fwd_kernel(const int*    __restrict__ stm_idx,    // [BATCH, NNZ]
                     const int*    __restrict__ nstm_idx,   // [BATCH, NNZ]
                     const float*  __restrict__ values,     // [BATCH, NNZ]
                     const float4* __restrict__ W_ft,       // [FT_IN, FT_OUT/4]
                     const float4* __restrict__ b_ft,       // [FT_OUT/4]
                     const float*  __restrict__ W_out,      // [2*FT_OUT]
                     const float*  __restrict__ b_out,      // [1]
                     float*        __restrict__ out)        // [BATCH]
{
    const int b = blockIdx.x;
    const int t = threadIdx.x;            // 0..127 -> float4 column slot
    const int C = FT_OUT / 4;             // 128 float4 per feature row

    // pre-scaled row offsets (idx * C) for both tables, plus values
    __shared__ int   s_off[2 * NNZ];
    __shared__ float s_val[NNZ];
    __shared__ float s_red[NTHREADS / 32];

    if (t < NNZ) {
        s_off[t]        = stm_idx [b * NNZ + t] * C;
        s_off[NNZ + t]  = nstm_idx[b * NNZ + t] * C;
        s_val[t]        = values  [b * NNZ + t];
    }
    __syncthreads();

    float4 acc_s = make_float4(0.f, 0.f, 0.f, 0.f);
    float4 acc_n = make_float4(0.f, 0.f, 0.f, 0.f);

    #pragma unroll
    for (int k = 0; k < NNZ; k++) {
        const float  v  = s_val[k];
        const float4 ws = __ldg(&W_ft[s_off[k]       + t]);
        const float4 wn = __ldg(&W_ft[s_off[NNZ + k] + t]);
        acc_s.x = fmaf(v, ws.x, acc_s.x);
        acc_s.y = fmaf(v, ws.y, acc_s.y);
        acc_s.z = fmaf(v, ws.z, acc_s.z);
        acc_s.w = fmaf(v, ws.w, acc_s.w);
        acc_n.x = fmaf(v, wn.x, acc_n.x);
        acc_n.y = fmaf(v, wn.y, acc_n.y);
        acc_n.z = fmaf(v, wn.z, acc_n.z);
        acc_n.w = fmaf(v, wn.w, acc_n.w);
    }

    // bias + clamp [0,1]
    const float4 bb = __ldg(&b_ft[t]);
    float hs0 = fminf(fmaxf(acc_s.x + bb.x, 0.f), 1.f);
    float hs1 = fminf(fmaxf(acc_s.y + bb.y, 0.f), 1.f);
    float hs2 = fminf(fmaxf(acc_s.z + bb.z, 0.f), 1.f);
    float hs3 = fminf(fmaxf(acc_s.w + bb.w, 0.f), 1.f);
    float hn0 = fminf(fmaxf(acc_n.x + bb.x, 0.f), 1.f);
    float hn1 = fminf(fmaxf(acc_n.y + bb.y, 0.f), 1.f);
    float hn2 = fminf(fmaxf(acc_n.z + bb.z, 0.f), 1.f);
    float hn3 = fminf(fmaxf(acc_n.w + bb.w, 0.f), 1.f);

    // dot with W_out slices (hidden = [stm | nstm], nstm half offset by FT_OUT)
    const float4 wo_s = __ldg((const float4*)&W_out[4 * t]);
    const float4 wo_n = __ldg((const float4*)&W_out[FT_OUT + 4 * t]);
    float p = hs0 * wo_s.x + hs1 * wo_s.y + hs2 * wo_s.z + hs3 * wo_s.w
            + hn0 * wo_n.x + hn1 * wo_n.y + hn2 * wo_n.z + hn3 * wo_n.w;

    // warp reduce
    #pragma unroll
    for (int off = 16; off > 0; off >>= 1)
        p += __shfl_xor_sync(0xFFFFFFFFu, p, off);

    if ((t & 31) == 0) s_red[t >> 5] = p;
    __syncthreads();

    if (t == 0) {
        float s = s_red[0] + s_red[1] + s_red[2] + s_red[3] + __ldg(b_out);
        out[b] = 1.0f / (1.0f + expf(-s));
    }
}

extern "C" void kernel_launch(void* const* d_in, const int* in_sizes, int n_in,
                              void* d_out, int out_size)
{
    const int*    stm_idx  = (const int*)   d_in[0];
    const int*    nstm_idx = (const int*)   d_in[1];
    const float*  values   = (const float*) d_in[2];
    const float4* W_ft     = (const float4*)d_in[3];
    const float4* b_ft     = (const float4*)d_in[4];
    const float*  W_out    = (const float*) d_in[5];
    const float*  b_out    = (const float*) d_in[6];
    float*        out      = (float*)       d_out;

    nnue_fwd_kernel<<<BATCH, NTHREADS>>>(stm_idx, nstm_idx, values,
                                         W_ft, b_ft, W_out, b_out, out);
}